// round 14
// baseline (speedup 1.0000x reference)
#include <cuda_runtime.h>
#include <cuda_bf16.h>
#include <math.h>
#include <stdint.h>

// ---------------- problem dims (fixed) ----------------
#define BDIM   8
#define TDIM   4096
#define HEADSN 8
#define ES     64
#define EMBN   512
#define MF     32
#define HIDN   2048
#define NTOK   (BDIM*TDIM)        // 32768
#define NROWH  (NTOK*HEADSN)      // 262144

// ---------------- scratch (device globals) ----------------
__device__ float g_kq  [NROWH*128];    // k|q per (token,head), stride 128
__device__ float g_kp  [NROWH*MF];
__device__ float g_qp  [NROWH*MF];
__device__ float g_v   [NROWH*ES];     // [b*8+h][t][e]
__device__ float g_ks  [64*MF];
__device__ float g_kptv[64*ES*MF];
__device__ float g_x1  [NTOK*EMBN];

__device__ __nv_bfloat16 g_y_hi [NTOK*EMBN];
__device__ __nv_bfloat16 g_y_lo [NTOK*EMBN];
__device__ __nv_bfloat16 g_h2_hi[NTOK*EMBN];   // LN1 out, then LN2 out (sequential reuse)
__device__ __nv_bfloat16 g_h2_lo[NTOK*EMBN];
__device__ __nv_bfloat16 g_hd_hi[NTOK*HIDN];
__device__ __nv_bfloat16 g_hd_lo[NTOK*HIDN];

__device__ __nv_bfloat16 g_pw_hi[EMBN*EMBN];
__device__ __nv_bfloat16 g_pw_lo[EMBN*EMBN];
__device__ __nv_bfloat16 g_w1_hi[HIDN*EMBN];
__device__ __nv_bfloat16 g_w1_lo[HIDN*EMBN];
__device__ __nv_bfloat16 g_w2_hi[EMBN*HIDN];
__device__ __nv_bfloat16 g_w2_lo[EMBN*HIDN];
__device__ __nv_bfloat16 g_kw_hi[256*64];      // kqv_w padded 192->256 rows
__device__ __nv_bfloat16 g_kw_lo[256*64];

// ---------------- helpers ----------------
__device__ __forceinline__ uint32_t smem_u32(const void* p) {
    uint32_t a;
    asm("{ .reg .u64 t; cvta.to.shared.u64 t, %1; cvt.u32.u64 %0, t; }" : "=r"(a) : "l"(p));
    return a;
}
__device__ __forceinline__ void cp16(uint32_t saddr, const void* g) {
    asm volatile("cp.async.cg.shared.global [%0], [%1], 16;" :: "r"(saddr), "l"(g) : "memory");
}
__device__ __forceinline__ void ldsm4(uint32_t* r, uint32_t addr) {
    asm volatile("ldmatrix.sync.aligned.m8n8.x4.shared.b16 {%0,%1,%2,%3}, [%4];"
        : "=r"(r[0]), "=r"(r[1]), "=r"(r[2]), "=r"(r[3]) : "r"(addr));
}
__device__ __forceinline__ void hmma(float* d, const uint32_t* a, const uint32_t* b) {
    asm volatile("mma.sync.aligned.m16n8k16.row.col.f32.bf16.bf16.f32 "
        "{%0,%1,%2,%3}, {%4,%5,%6,%7}, {%8,%9}, {%0,%1,%2,%3};"
        : "+f"(d[0]), "+f"(d[1]), "+f"(d[2]), "+f"(d[3])
        : "r"(a[0]), "r"(a[1]), "r"(a[2]), "r"(a[3]), "r"(b[0]), "r"(b[1]));
}
__device__ __forceinline__ float gelu_f(float v) {
    return 0.5f * v * (1.0f + erff(v * 0.7071067811865476f));
}
__device__ __forceinline__ void split_bf16(float v, __nv_bfloat16& hi, __nv_bfloat16& lo) {
    hi = __float2bfloat16(v);
    lo = __float2bfloat16(v - __bfloat162float(hi));
}
// f32x2 packed FMA
__device__ __forceinline__ unsigned long long pk2(float a) {
    unsigned long long r; unsigned int u = __float_as_uint(a);
    asm("mov.b64 %0, {%1, %1};" : "=l"(r) : "r"(u));
    return r;
}
__device__ __forceinline__ void fma2(unsigned long long& d, unsigned long long a, unsigned long long b) {
    asm("fma.rn.f32x2 %0, %1, %2, %0;" : "+l"(d) : "l"(a), "l"(b));
}
__device__ __forceinline__ void upk2(unsigned long long v, float& lo, float& hi) {
    unsigned int a, b;
    asm("mov.b64 {%0, %1}, %2;" : "=r"(a), "=r"(b) : "l"(v));
    lo = __uint_as_float(a); hi = __uint_as_float(b);
}

// ================= HMMA split-bf16 GEMM (128x128 CTA, 3 stages, occ 2, full-B regs) =================
// C[m][n] = sum_k A[m][k]*W[n][k]; A,W as bf16 hi/lo pairs (3-product emulation).
// CTA tile 128x128, BK=32, STAGES=3, 256 threads, warp tile 32x64 (warpM=wid&3, warpN=wid>>2).
// EPI 1: o_hi/o_lo = bf16split(gelu(acc+bias))
// EPI 2: outf = acc+bias+resid (f32)
// EPI 3: kqv: cols<128 -> outf (k|q, stride 128); 128..191 -> vout scatter; >=192 dropped
#define MM_STAGES 3
#define MM_STAGE_BYTES 32768     // A hi/lo 8KB+8KB, B hi/lo 8KB+8KB
#define MM_SMEM (MM_STAGES * MM_STAGE_BYTES)

__device__ __forceinline__ uint32_t swz(int row, int chunk) {
    return (uint32_t)(row * 64 + ((chunk ^ ((row >> 1) & 3)) << 4));
}
__device__ __forceinline__ uint32_t addrA(uint32_t base, int lane, int ks) {
    int grp = lane >> 3;
    int row = (lane & 7) + ((grp & 1) << 3);
    int chunk = (ks << 1) + (grp >> 1);
    return base + swz(row, chunk);
}
__device__ __forceinline__ uint32_t addrB(uint32_t base, int lane, int ks) {
    int grp = lane >> 3;
    int row = (lane & 7) + ((grp >> 1) << 3);
    int chunk = (ks << 1) + (grp & 1);
    return base + swz(row, chunk);
}

__device__ __forceinline__ void mm_load_stage(
    uint32_t st, const char* Ah, const char* Al, const char* Bh, const char* Bl,
    long rsb, long kb2, int tid) {
    int lr = tid >> 1, lc0 = (tid & 1) * 2;
    long go = (long)lr * rsb + kb2;
#pragma unroll
    for (int j = 0; j < 2; j++) {
        int c = lc0 + j;
        uint32_t sw = swz(lr, c);
        cp16(st + sw,         Ah + go + c * 16);
        cp16(st + 8192 + sw,  Al + go + c * 16);
        cp16(st + 16384 + sw, Bh + go + c * 16);
        cp16(st + 24576 + sw, Bl + go + c * 16);
    }
}

template<int EPI>
__global__ void __launch_bounds__(256, 2)
mm_gemm(const __nv_bfloat16* __restrict__ a_hi, const __nv_bfloat16* __restrict__ a_lo,
        const __nv_bfloat16* __restrict__ w_hi, const __nv_bfloat16* __restrict__ w_lo,
        const float* __restrict__ bias, const float* __restrict__ resid,
        float* __restrict__ outf, __nv_bfloat16* __restrict__ o_hi, __nv_bfloat16* __restrict__ o_lo,
        float* __restrict__ vout, int N, int K) {
    extern __shared__ char smem[];
    uint32_t sb = smem_u32(smem);
    int tid = threadIdx.x, wid = tid >> 5, lane = tid & 31;

    // supertile swizzle: 16 M-tiles per group
    int gn = N >> 7;
    int per = 16 * gn;
    int grp_ = blockIdx.x / per, rem = blockIdx.x - grp_ * per;
    int m0 = (grp_ * 16 + (rem & 15)) * 128;
    int n0 = (rem >> 4) * 128;

    const long rsb = (long)K * 2;
    const char* Ah = (const char*)a_hi + (long)m0 * rsb;
    const char* Al = (const char*)a_lo + (long)m0 * rsb;
    const char* Bh = (const char*)w_hi + (long)n0 * rsb;
    const char* Bl = (const char*)w_lo + (long)n0 * rsb;
    int KT = K >> 5;

    // prologue: fill STAGES-1 stages
#pragma unroll
    for (int s = 0; s < MM_STAGES - 1; s++) {
        if (s < KT) mm_load_stage(sb + s * MM_STAGE_BYTES, Ah, Al, Bh, Bl, rsb, (long)s * 64, tid);
        asm volatile("cp.async.commit_group;" ::: "memory");
    }

    int warpM = wid & 3, warpN = wid >> 2;
    float acc[2][8][4];
#pragma unroll
    for (int mt = 0; mt < 2; mt++)
#pragma unroll
        for (int nt = 0; nt < 8; nt++)
#pragma unroll
            for (int q = 0; q < 4; q++) acc[mt][nt][q] = 0.f;

    int sc = 0, sp = MM_STAGES - 1;
    for (int kt = 0; kt < KT; kt++) {
        asm volatile("cp.async.wait_group %0;" :: "n"(MM_STAGES - 2) : "memory");
        __syncthreads();
        int pf = kt + MM_STAGES - 1;
        if (pf < KT)
            mm_load_stage(sb + sp * MM_STAGE_BYTES, Ah, Al, Bh, Bl, rsb, (long)pf * 64, tid);
        asm volatile("cp.async.commit_group;" ::: "memory");

        uint32_t st = sb + sc * MM_STAGE_BYTES;
        uint32_t aH = st + (warpM * 32) * 64;
        uint32_t aL = aH + 8192;
        uint32_t bH = st + 16384 + (warpN * 64) * 64;
        uint32_t bL = bH + 8192;

#pragma unroll
        for (int ks = 0; ks < 2; ks++) {
            uint32_t ah[2][4], al[2][4], bh[4][4], bl[4][4];
#pragma unroll
            for (int mt = 0; mt < 2; mt++) {
                ldsm4(ah[mt], addrA(aH + mt * 16 * 64, lane, ks));
                ldsm4(al[mt], addrA(aL + mt * 16 * 64, lane, ks));
            }
#pragma unroll
            for (int np = 0; np < 4; np++) {
                ldsm4(bh[np], addrB(bH + np * 1024, lane, ks));
                ldsm4(bl[np], addrB(bL + np * 1024, lane, ks));
            }
#pragma unroll
            for (int nt = 0; nt < 8; nt++) {
                const uint32_t* bhp = &bh[nt >> 1][(nt & 1) * 2];
                const uint32_t* blp = &bl[nt >> 1][(nt & 1) * 2];
#pragma unroll
                for (int mt = 0; mt < 2; mt++) {
                    hmma(acc[mt][nt], ah[mt], bhp);
                    hmma(acc[mt][nt], ah[mt], blp);
                    hmma(acc[mt][nt], al[mt], bhp);
                }
            }
        }
        sc = (sc + 1 == MM_STAGES) ? 0 : sc + 1;
        sp = (sp + 1 == MM_STAGES) ? 0 : sp + 1;
    }

    // ---------------- epilogue ----------------
    int r = lane >> 2, cq = (lane & 3) * 2;
    if (EPI == 3 && n0 + warpN * 64 >= 192) return;   // kqv pad cols dropped
#pragma unroll
    for (int mt = 0; mt < 2; mt++) {
#pragma unroll
        for (int half = 0; half < 2; half++) {
            long row = m0 + warpM * 32 + mt * 16 + half * 8 + r;
            if (EPI == 3) {
                long bt = row >> 3; int hh = (int)(row & 7);
                int bb = (int)(bt >> 12), tt = (int)(bt & 4095);
                float* kqrow = outf + row * 128;
                float* vrow  = vout + (((long)(bb * 8 + hh) * TDIM + tt) << 6);
#pragma unroll
                for (int nt = 0; nt < 8; nt++) {
                    int col = n0 + warpN * 64 + nt * 8 + cq;
                    float v0 = acc[mt][nt][half * 2 + 0] + bias[col];
                    float v1 = acc[mt][nt][half * 2 + 1] + bias[col + 1];
                    if (col < 128) *(float2*)(kqrow + col) = make_float2(v0, v1);
                    else           *(float2*)(vrow + col - 128) = make_float2(v0, v1);
                }
            } else {
#pragma unroll
                for (int nt = 0; nt < 8; nt++) {
                    int col = n0 + warpN * 64 + nt * 8 + cq;
                    float v0 = acc[mt][nt][half * 2 + 0] + bias[col];
                    float v1 = acc[mt][nt][half * 2 + 1] + bias[col + 1];
                    if (EPI == 1) {
                        v0 = gelu_f(v0); v1 = gelu_f(v1);
                        __nv_bfloat16 h0, l0, h1, l1;
                        split_bf16(v0, h0, l0); split_bf16(v1, h1, l1);
                        *(__nv_bfloat162*)(o_hi + row * N + col) = __halves2bfloat162(h0, h1);
                        *(__nv_bfloat162*)(o_lo + row * N + col) = __halves2bfloat162(l0, l1);
                    } else {
                        float2 rv = *(const float2*)(resid + row * N + col);
                        *(float2*)(outf + row * N + col) = make_float2(v0 + rv.x, v1 + rv.y);
                    }
                }
            }
        }
    }
}

// ---------------- weight split: f32 -> bf16 hi/lo (with zero pad) ----------------
__global__ void split_kernel(const float* __restrict__ w, __nv_bfloat16* __restrict__ hi,
                             __nv_bfloat16* __restrict__ lo, int nvalid, int ntotal) {
    int i = blockIdx.x * 256 + threadIdx.x;
    if (i < ntotal) {
        float v = (i < nvalid) ? w[i] : 0.f;
        __nv_bfloat16 h, l;
        split_bf16(v, h, l);
        hi[i] = h; lo[i] = l;
    }
}

// ---------------- LayerNorm (bf16 hi/lo out) ----------------
__global__ void ln_split_kernel(const float* __restrict__ x, const float* __restrict__ g,
                                const float* __restrict__ b,
                                __nv_bfloat16* __restrict__ ohi, __nv_bfloat16* __restrict__ olo) {
    int wid = threadIdx.x >> 5, lane = threadIdx.x & 31;
    long row = (long)blockIdx.x * 8 + wid;
    const float4* xr = (const float4*)(x + row * EMBN);
    float4 v[4];
    float s = 0.f, sq = 0.f;
#pragma unroll
    for (int j = 0; j < 4; j++) {
        v[j] = xr[lane + 32 * j];
        s  += v[j].x + v[j].y + v[j].z + v[j].w;
        sq += v[j].x*v[j].x + v[j].y*v[j].y + v[j].z*v[j].z + v[j].w*v[j].w;
    }
#pragma unroll
    for (int o = 16; o; o >>= 1) {
        s  += __shfl_xor_sync(0xffffffffu, s,  o);
        sq += __shfl_xor_sync(0xffffffffu, sq, o);
    }
    float mu = s * (1.0f / EMBN);
    float var = sq * (1.0f / EMBN) - mu * mu;
    float rsv = rsqrtf(var + 1e-5f);
#pragma unroll
    for (int j = 0; j < 4; j++) {
        int fi = lane + 32 * j;
        float4 g4 = ((const float4*)g)[fi];
        float4 b4 = ((const float4*)b)[fi];
        float o0 = (v[j].x - mu) * rsv * g4.x + b4.x;
        float o1 = (v[j].y - mu) * rsv * g4.y + b4.y;
        float o2 = (v[j].z - mu) * rsv * g4.z + b4.z;
        float o3 = (v[j].w - mu) * rsv * g4.w + b4.w;
        __nv_bfloat16 h0,l0,h1,l1,h2,l2,h3,l3;
        split_bf16(o0,h0,l0); split_bf16(o1,h1,l1); split_bf16(o2,h2,l2); split_bf16(o3,h3,l3);
        long base = row * EMBN + fi * 4;
        *(__nv_bfloat162*)(ohi + base)     = __halves2bfloat162(h0, h1);
        *(__nv_bfloat162*)(ohi + base + 2) = __halves2bfloat162(h2, h3);
        *(__nv_bfloat162*)(olo + base)     = __halves2bfloat162(l0, l1);
        *(__nv_bfloat162*)(olo + base + 2) = __halves2bfloat162(l2, l3);
    }
}

// ---------------- prm_exp (k,q only; stride-128 input) ----------------
__global__ void prm_kernel(const float* __restrict__ kq, const float* __restrict__ w,
                           float* __restrict__ kp, float* __restrict__ qp) {
    __shared__ float w_s[32 * 65];
    __shared__ float z_s[8][128];
    int tid = threadIdx.x;
    for (int i = tid; i < MF * ES; i += 256)
        w_s[(i >> 6) * 65 + (i & 63)] = w[i];
    int wid = tid >> 5, lane = tid & 31;
    long row = (long)blockIdx.x * 8 + wid;
    const float* r = kq + row * 128;
    float k0 = r[lane],       k1 = r[lane + 32];
    float q0 = r[lane + 64],  q1 = r[lane + 96];
    int  h  = (int)(row & 7);
    long bt = row >> 3;
    int  b  = (int)(bt >> 12);
    int  t  = (int)(bt & 4095);
    z_s[wid][lane]      = k0;  z_s[wid][lane + 32] = k1;
    z_s[wid][64 + lane] = q0;  z_s[wid][96 + lane] = q1;
    float sk = k0 * k0 + k1 * k1;
    float sq = q0 * q0 + q1 * q1;
#pragma unroll
    for (int o = 16; o; o >>= 1) {
        sk += __shfl_xor_sync(0xffffffffu, sk, o);
        sq += __shfl_xor_sync(0xffffffffu, sq, o);
    }
    float xdk = 0.5f * sk, xdq = 0.5f * sq;
    __syncthreads();
    const float* wm = &w_s[lane * 65];
    float wk = 0.f, wq = 0.f;
#pragma unroll 8
    for (int e = 0; e < 64; e++) {
        float we = wm[e];
        wk += we * z_s[wid][e];
        wq += we * z_s[wid][64 + e];
    }
    const float rsM = 0.17677669529663687f;
    kp[((long)(b * 8 + h) * TDIM + t) * MF + lane] = expf(wk - xdk) * rsM;
    qp[row * MF + lane] = expf(wq - xdq) * rsM;
}

// ---------------- kptv[bh][e][m] = sum_t v[bh][t][e]*kp[bh][t][m]; ks = sum_t kp ----------------
// 16 segments of 256 tokens per bh for better latency hiding
__global__ void kptv_kernel(const float* __restrict__ kp, const float* __restrict__ v,
                            float* __restrict__ kptv, float* __restrict__ ks) {
    int bh = blockIdx.x, seg = blockIdx.y;
    const float* kpb = kp + ((long)bh * TDIM + seg * 256) * MF;
    const float* vb  = v  + ((long)bh * TDIM + seg * 256) * ES;
    __shared__ float kc[16][32];
    __shared__ float vc[16][64];
    int tid = threadIdx.x;
    int m = tid & 31, eg = tid >> 5;
    unsigned long long acc2[4] = {0ull, 0ull, 0ull, 0ull};
    float ksa = 0.f;
    for (int c = 0; c < 16; c++) {
        __syncthreads();
#pragma unroll
        for (int i = 0; i < 2; i++) {
            int idx = tid + i * 256;
            kc[idx >> 5][idx & 31] = kpb[c * 512 + idx];
        }
#pragma unroll
        for (int i = 0; i < 4; i++) {
            int idx = tid + i * 256;
            vc[idx >> 6][idx & 63] = vb[c * 1024 + idx];
        }
        __syncthreads();
#pragma unroll
        for (int tt = 0; tt < 16; tt++) {
            float kv = kc[tt][m];
            if (eg == 0) ksa += kv;
            unsigned long long kv2 = pk2(kv);
#pragma unroll
            for (int j = 0; j < 4; j++)
                fma2(acc2[j], kv2, *(const unsigned long long*)&vc[tt][eg * 8 + j * 2]);
        }
    }
#pragma unroll
    for (int j = 0; j < 4; j++) {
        float a0, a1;
        upk2(acc2[j], a0, a1);
        atomicAdd(&kptv[(long)bh * (ES * MF) + (eg * 8 + j * 2) * MF + m], a0);
        atomicAdd(&kptv[(long)bh * (ES * MF) + (eg * 8 + j * 2 + 1) * MF + m], a1);
    }
    if (eg == 0) atomicAdd(&ks[bh * MF + m], ksa);
}

// ---------------- y = (qp @ kptv^T)/D -> bf16 hi/lo ----------------
__global__ void y_kernel(const float* __restrict__ qp, const float* __restrict__ kptv,
                         const float* __restrict__ ks,
                         __nv_bfloat16* __restrict__ yhi, __nv_bfloat16* __restrict__ ylo) {
    int tset = blockIdx.x, b = blockIdx.y, hh = blockIdx.z;
    __shared__ float kv_s[4 * 64 * 33];
    __shared__ float ks_s[4 * 32];
    int tid = threadIdx.x;
    for (int i = tid; i < 4 * 64 * 32; i += 256) {
        int h = i >> 11, e = (i >> 5) & 63, m = i & 31;
        kv_s[(h * 64 + e) * 33 + m] = kptv[((long)(b * 8 + hh * 4 + h) * 64 + e) * 32 + m];
    }
    if (tid < 128) ks_s[tid] = ks[(b * 8 + hh * 4) * 32 + tid];
    __syncthreads();
    int wid = tid >> 5, lane = tid & 31;
    int t = tset * 8 + wid;
    long row = (long)b * TDIM + t;
    const float* qpp = qp + row * (HEADSN * MF) + hh * 128;
    float qpr[4];
#pragma unroll
    for (int j = 0; j < 4; j++) qpr[j] = qpp[j * 32 + lane];
    long ybase = row * EMBN + hh * 256;
#pragma unroll
    for (int h = 0; h < 4; h++) {
        float d = qpr[h] * ks_s[h * 32 + lane];
#pragma unroll
        for (int o = 16; o; o >>= 1) d += __shfl_xor_sync(0xffffffffu, d, o);
        float invd = 1.0f / d;
        const float* kvh = &kv_s[h * 64 * 33];
        float a0 = 0.f, a1 = 0.f;
#pragma unroll 8
        for (int m = 0; m < 32; m++) {
            float qm = __shfl_sync(0xffffffffu, qpr[h], m);
            a0 += kvh[lane * 33 + m] * qm;
            a1 += kvh[(lane + 32) * 33 + m] * qm;
        }
        float o0 = a0 * invd, o1 = a1 * invd;
        __nv_bfloat16 h0, l0, h1, l1;
        split_bf16(o0, h0, l0); split_bf16(o1, h1, l1);
        yhi[ybase + h * 64 + lane]      = h0;
        ylo[ybase + h * 64 + lane]      = l0;
        yhi[ybase + h * 64 + 32 + lane] = h1;
        ylo[ybase + h * 64 + 32 + lane] = l1;
    }
}

// ---------------- launcher ----------------
extern "C" void kernel_launch(void* const* d_in, const int* in_sizes, int n_in,
                              void* d_out, int out_size) {
    const float* x      = (const float*)d_in[0];
    const float* w      = (const float*)d_in[1];
    const float* kqv_w  = (const float*)d_in[2];
    const float* kqv_b  = (const float*)d_in[3];
    const float* proj_w = (const float*)d_in[4];
    const float* proj_b = (const float*)d_in[5];
    const float* ln1_g  = (const float*)d_in[6];
    const float* ln1_b  = (const float*)d_in[7];
    const float* ln2_g  = (const float*)d_in[8];
    const float* ln2_b  = (const float*)d_in[9];
    const float* mlp_w1 = (const float*)d_in[10];
    const float* mlp_b1 = (const float*)d_in[11];
    const float* mlp_w2 = (const float*)d_in[12];
    const float* mlp_b2 = (const float*)d_in[13];
    float* out = (float*)d_out;

    float *pkq, *pkp, *pqp, *pv, *pks, *pkptv, *px1;
    __nv_bfloat16 *pyh, *pyl, *ph2h, *ph2l, *phdh, *phdl;
    __nv_bfloat16 *ppwh, *ppwl, *pw1h, *pw1l, *pw2h, *pw2l, *pkwh, *pkwl;
    cudaGetSymbolAddress((void**)&pkq,   g_kq);
    cudaGetSymbolAddress((void**)&pkp,   g_kp);
    cudaGetSymbolAddress((void**)&pqp,   g_qp);
    cudaGetSymbolAddress((void**)&pv,    g_v);
    cudaGetSymbolAddress((void**)&pks,   g_ks);
    cudaGetSymbolAddress((void**)&pkptv, g_kptv);
    cudaGetSymbolAddress((void**)&px1,   g_x1);
    cudaGetSymbolAddress((void**)&pyh,   g_y_hi);
    cudaGetSymbolAddress((void**)&pyl,   g_y_lo);
    cudaGetSymbolAddress((void**)&ph2h,  g_h2_hi);
    cudaGetSymbolAddress((void**)&ph2l,  g_h2_lo);
    cudaGetSymbolAddress((void**)&phdh,  g_hd_hi);
    cudaGetSymbolAddress((void**)&phdl,  g_hd_lo);
    cudaGetSymbolAddress((void**)&ppwh,  g_pw_hi);
    cudaGetSymbolAddress((void**)&ppwl,  g_pw_lo);
    cudaGetSymbolAddress((void**)&pw1h,  g_w1_hi);
    cudaGetSymbolAddress((void**)&pw1l,  g_w1_lo);
    cudaGetSymbolAddress((void**)&pw2h,  g_w2_hi);
    cudaGetSymbolAddress((void**)&pw2l,  g_w2_lo);
    cudaGetSymbolAddress((void**)&pkwh,  g_kw_hi);
    cudaGetSymbolAddress((void**)&pkwl,  g_kw_lo);

    cudaFuncSetAttribute(mm_gemm<1>, cudaFuncAttributeMaxDynamicSharedMemorySize, MM_SMEM);
    cudaFuncSetAttribute(mm_gemm<2>, cudaFuncAttributeMaxDynamicSharedMemorySize, MM_SMEM);
    cudaFuncSetAttribute(mm_gemm<3>, cudaFuncAttributeMaxDynamicSharedMemorySize, MM_SMEM);

    // zero reduction scratch (async memset is graph-capturable)
    cudaMemsetAsync(pkptv, 0, 64 * ES * MF * sizeof(float));
    cudaMemsetAsync(pks,   0, 64 * MF * sizeof(float));

    // weight splits (kqv_w padded 192 -> 256 rows)
    split_kernel<<<(256*64 + 255)/256, 256>>>(kqv_w, pkwh, pkwl, 192*64, 256*64);
    split_kernel<<<(EMBN*EMBN + 255)/256, 256>>>(proj_w, ppwh, ppwl, EMBN*EMBN, EMBN*EMBN);
    split_kernel<<<(HIDN*EMBN + 255)/256, 256>>>(mlp_w1, pw1h, pw1l, HIDN*EMBN, HIDN*EMBN);
    split_kernel<<<(EMBN*HIDN + 255)/256, 256>>>(mlp_w2, pw2h, pw2l, EMBN*HIDN, EMBN*HIDN);

    // 1) LN1 -> bf16 hi/lo
    ln_split_kernel<<<NTOK / 8, 256>>>(x, ln1_g, ln1_b, ph2h, ph2l);
    // 2) kqv GEMM (HMMA, EPI3): k|q -> g_kq, v -> g_v scatter (N padded to 256)
    mm_gemm<3><<<(NROWH/128) * 2, 256, MM_SMEM>>>(
        ph2h, ph2l, pkwh, pkwl, kqv_b, nullptr, pkq, nullptr, nullptr, pv, 256, 64);
    // 3) random features
    prm_kernel<<<NROWH / 8, 256>>>(pkq, w, pkp, pqp);
    // 4) kptv + ks (16 segments of 256 tokens)
    kptv_kernel<<<dim3(64, 16), 256>>>(pkp, pv, pkptv, pks);
    // 5) y -> bf16 hi/lo
    y_kernel<<<dim3(TDIM / 8, BDIM, 2), 256>>>(pqp, pkptv, pks, pyh, pyl);
    // 6) proj (HMMA) + bias + resid(x) -> x1
    mm_gemm<2><<<(NTOK/128) * (EMBN/128), 256, MM_SMEM>>>(
        pyh, pyl, ppwh, ppwl, proj_b, x, px1, nullptr, nullptr, nullptr, EMBN, EMBN);
    // 7) LN2 -> bf16 hi/lo
    ln_split_kernel<<<NTOK / 8, 256>>>(px1, ln2_g, ln2_b, ph2h, ph2l);
    // 8) MLP1 (HMMA) + bias + gelu -> hid bf16 hi/lo
    mm_gemm<1><<<(NTOK/128) * (HIDN/128), 256, MM_SMEM>>>(
        ph2h, ph2l, pw1h, pw1l, mlp_b1, nullptr, nullptr, phdh, phdl, nullptr, HIDN, EMBN);
    // 9) MLP2 (HMMA) + bias + resid(x1) -> out
    mm_gemm<2><<<(NTOK/128) * (EMBN/128), 256, MM_SMEM>>>(
        phdh, phdl, pw2h, pw2l, mlp_b2, px1, out, nullptr, nullptr, nullptr, EMBN, HIDN);
}

// round 15
// speedup vs baseline: 1.0225x; 1.0225x over previous
#include <cuda_runtime.h>
#include <cuda_bf16.h>
#include <math.h>
#include <stdint.h>

// ---------------- problem dims (fixed) ----------------
#define BDIM   8
#define TDIM   4096
#define HEADSN 8
#define ES     64
#define EMBN   512
#define MF     32
#define HIDN   2048
#define NTOK   (BDIM*TDIM)        // 32768
#define NROWH  (NTOK*HEADSN)      // 262144

// ---------------- scratch (device globals) ----------------
__device__ float g_kq  [NROWH*128];    // k|q per (token,head), stride 128
__device__ float g_kp  [NROWH*MF];
__device__ float g_qp  [NROWH*MF];
__device__ float g_v   [NROWH*ES];     // [b*8+h][t][e]
__device__ float g_ks  [64*MF];
__device__ float g_kptv[64*ES*MF];
__device__ float g_x1  [NTOK*EMBN];

__device__ __nv_bfloat16 g_y_hi [NTOK*EMBN];
__device__ __nv_bfloat16 g_y_lo [NTOK*EMBN];
__device__ __nv_bfloat16 g_h2_hi[NTOK*EMBN];   // LN1 out, then LN2 out (sequential reuse)
__device__ __nv_bfloat16 g_h2_lo[NTOK*EMBN];
__device__ __nv_bfloat16 g_hd_hi[NTOK*HIDN];
__device__ __nv_bfloat16 g_hd_lo[NTOK*HIDN];

__device__ __nv_bfloat16 g_pw_hi[EMBN*EMBN];
__device__ __nv_bfloat16 g_pw_lo[EMBN*EMBN];
__device__ __nv_bfloat16 g_w1_hi[HIDN*EMBN];
__device__ __nv_bfloat16 g_w1_lo[HIDN*EMBN];
__device__ __nv_bfloat16 g_w2_hi[EMBN*HIDN];
__device__ __nv_bfloat16 g_w2_lo[EMBN*HIDN];
__device__ __nv_bfloat16 g_kw_hi[256*64];      // kqv_w padded 192->256 rows
__device__ __nv_bfloat16 g_kw_lo[256*64];

// ---------------- helpers ----------------
__device__ __forceinline__ uint32_t smem_u32(const void* p) {
    uint32_t a;
    asm("{ .reg .u64 t; cvta.to.shared.u64 t, %1; cvt.u32.u64 %0, t; }" : "=r"(a) : "l"(p));
    return a;
}
__device__ __forceinline__ void cp16(uint32_t saddr, const void* g) {
    asm volatile("cp.async.cg.shared.global [%0], [%1], 16;" :: "r"(saddr), "l"(g) : "memory");
}
__device__ __forceinline__ void ldsm4(uint32_t* r, uint32_t addr) {
    asm volatile("ldmatrix.sync.aligned.m8n8.x4.shared.b16 {%0,%1,%2,%3}, [%4];"
        : "=r"(r[0]), "=r"(r[1]), "=r"(r[2]), "=r"(r[3]) : "r"(addr));
}
__device__ __forceinline__ void hmma(float* d, const uint32_t* a, const uint32_t* b) {
    asm volatile("mma.sync.aligned.m16n8k16.row.col.f32.bf16.bf16.f32 "
        "{%0,%1,%2,%3}, {%4,%5,%6,%7}, {%8,%9}, {%0,%1,%2,%3};"
        : "+f"(d[0]), "+f"(d[1]), "+f"(d[2]), "+f"(d[3])
        : "r"(a[0]), "r"(a[1]), "r"(a[2]), "r"(a[3]), "r"(b[0]), "r"(b[1]));
}
__device__ __forceinline__ float gelu_f(float v) {
    return 0.5f * v * (1.0f + erff(v * 0.7071067811865476f));
}
__device__ __forceinline__ void split_bf16(float v, __nv_bfloat16& hi, __nv_bfloat16& lo) {
    hi = __float2bfloat16(v);
    lo = __float2bfloat16(v - __bfloat162float(hi));
}
// f32x2 packed FMA
__device__ __forceinline__ unsigned long long pk2(float a) {
    unsigned long long r; unsigned int u = __float_as_uint(a);
    asm("mov.b64 %0, {%1, %1};" : "=l"(r) : "r"(u));
    return r;
}
__device__ __forceinline__ void fma2(unsigned long long& d, unsigned long long a, unsigned long long b) {
    asm("fma.rn.f32x2 %0, %1, %2, %0;" : "+l"(d) : "l"(a), "l"(b));
}
__device__ __forceinline__ void upk2(unsigned long long v, float& lo, float& hi) {
    unsigned int a, b;
    asm("mov.b64 {%0, %1}, %2;" : "=r"(a), "=r"(b) : "l"(v));
    lo = __uint_as_float(a); hi = __uint_as_float(b);
}

// ================= HMMA split-bf16 GEMM (128x128 CTA, 3 stages, occ 2, half-B regs) =================
// Product-major HMMA ordering: per B-half, 8 independent hmma per product group
// (breaks the 3-deep RAW chain on each accumulator that asm volatile pins in place).
// EPI 1: o_hi/o_lo = bf16split(gelu(acc+bias))
// EPI 2: outf = acc+bias+resid (f32)
// EPI 3: kqv: cols<128 -> outf (k|q, stride 128); 128..191 -> vout scatter; >=192 dropped
#define MM_STAGES 3
#define MM_STAGE_BYTES 32768     // A hi/lo 8KB+8KB, B hi/lo 8KB+8KB
#define MM_SMEM (MM_STAGES * MM_STAGE_BYTES)

__device__ __forceinline__ uint32_t swz(int row, int chunk) {
    return (uint32_t)(row * 64 + ((chunk ^ ((row >> 1) & 3)) << 4));
}
__device__ __forceinline__ uint32_t addrA(uint32_t base, int lane, int ks) {
    int grp = lane >> 3;
    int row = (lane & 7) + ((grp & 1) << 3);
    int chunk = (ks << 1) + (grp >> 1);
    return base + swz(row, chunk);
}
__device__ __forceinline__ uint32_t addrB(uint32_t base, int lane, int ks) {
    int grp = lane >> 3;
    int row = (lane & 7) + ((grp >> 1) << 3);
    int chunk = (ks << 1) + (grp & 1);
    return base + swz(row, chunk);
}

__device__ __forceinline__ void mm_load_stage(
    uint32_t st, const char* Ah, const char* Al, const char* Bh, const char* Bl,
    long rsb, long kb2, int tid) {
    int lr = tid >> 1, lc0 = (tid & 1) * 2;
    long go = (long)lr * rsb + kb2;
#pragma unroll
    for (int j = 0; j < 2; j++) {
        int c = lc0 + j;
        uint32_t sw = swz(lr, c);
        cp16(st + sw,         Ah + go + c * 16);
        cp16(st + 8192 + sw,  Al + go + c * 16);
        cp16(st + 16384 + sw, Bh + go + c * 16);
        cp16(st + 24576 + sw, Bl + go + c * 16);
    }
}

template<int EPI>
__global__ void __launch_bounds__(256, 2)
mm_gemm(const __nv_bfloat16* __restrict__ a_hi, const __nv_bfloat16* __restrict__ a_lo,
        const __nv_bfloat16* __restrict__ w_hi, const __nv_bfloat16* __restrict__ w_lo,
        const float* __restrict__ bias, const float* __restrict__ resid,
        float* __restrict__ outf, __nv_bfloat16* __restrict__ o_hi, __nv_bfloat16* __restrict__ o_lo,
        float* __restrict__ vout, int N, int K) {
    extern __shared__ char smem[];
    uint32_t sb = smem_u32(smem);
    int tid = threadIdx.x, wid = tid >> 5, lane = tid & 31;

    // supertile swizzle: 16 M-tiles per group
    int gn = N >> 7;
    int per = 16 * gn;
    int grp_ = blockIdx.x / per, rem = blockIdx.x - grp_ * per;
    int m0 = (grp_ * 16 + (rem & 15)) * 128;
    int n0 = (rem >> 4) * 128;

    const long rsb = (long)K * 2;
    const char* Ah = (const char*)a_hi + (long)m0 * rsb;
    const char* Al = (const char*)a_lo + (long)m0 * rsb;
    const char* Bh = (const char*)w_hi + (long)n0 * rsb;
    const char* Bl = (const char*)w_lo + (long)n0 * rsb;
    int KT = K >> 5;

    // prologue: fill STAGES-1 stages
#pragma unroll
    for (int s = 0; s < MM_STAGES - 1; s++) {
        if (s < KT) mm_load_stage(sb + s * MM_STAGE_BYTES, Ah, Al, Bh, Bl, rsb, (long)s * 64, tid);
        asm volatile("cp.async.commit_group;" ::: "memory");
    }

    int warpM = wid & 3, warpN = wid >> 2;
    float acc[2][8][4];
#pragma unroll
    for (int mt = 0; mt < 2; mt++)
#pragma unroll
        for (int nt = 0; nt < 8; nt++)
#pragma unroll
            for (int q = 0; q < 4; q++) acc[mt][nt][q] = 0.f;

    int sc = 0, sp = MM_STAGES - 1;
    for (int kt = 0; kt < KT; kt++) {
        asm volatile("cp.async.wait_group %0;" :: "n"(MM_STAGES - 2) : "memory");
        __syncthreads();
        int pf = kt + MM_STAGES - 1;
        if (pf < KT)
            mm_load_stage(sb + sp * MM_STAGE_BYTES, Ah, Al, Bh, Bl, rsb, (long)pf * 64, tid);
        asm volatile("cp.async.commit_group;" ::: "memory");

        uint32_t st = sb + sc * MM_STAGE_BYTES;
        uint32_t aH = st + (warpM * 32) * 64;
        uint32_t aL = aH + 8192;
        uint32_t bH = st + 16384 + (warpN * 64) * 64;
        uint32_t bL = bH + 8192;

#pragma unroll
        for (int ks = 0; ks < 2; ks++) {
            uint32_t ah[2][4], al[2][4];
#pragma unroll
            for (int mt = 0; mt < 2; mt++) {
                ldsm4(ah[mt], addrA(aH + mt * 16 * 64, lane, ks));
                ldsm4(al[mt], addrA(aL + mt * 16 * 64, lane, ks));
            }
            // B in two halves (register cap for occ 2); product-major hmma order
#pragma unroll
            for (int g = 0; g < 2; g++) {
                uint32_t bh2[2][4], bl2[2][4];
#pragma unroll
                for (int j = 0; j < 2; j++) {
                    ldsm4(bh2[j], addrB(bH + (g * 2 + j) * 1024, lane, ks));
                    ldsm4(bl2[j], addrB(bL + (g * 2 + j) * 1024, lane, ks));
                }
                // group 1: a_hi * b_hi  (8 independent)
#pragma unroll
                for (int ntl = 0; ntl < 4; ntl++) {
                    const uint32_t* bhp = &bh2[ntl >> 1][(ntl & 1) * 2];
#pragma unroll
                    for (int mt = 0; mt < 2; mt++)
                        hmma(acc[mt][g * 4 + ntl], ah[mt], bhp);
                }
                // group 2: a_hi * b_lo
#pragma unroll
                for (int ntl = 0; ntl < 4; ntl++) {
                    const uint32_t* blp = &bl2[ntl >> 1][(ntl & 1) * 2];
#pragma unroll
                    for (int mt = 0; mt < 2; mt++)
                        hmma(acc[mt][g * 4 + ntl], ah[mt], blp);
                }
                // group 3: a_lo * b_hi
#pragma unroll
                for (int ntl = 0; ntl < 4; ntl++) {
                    const uint32_t* bhp = &bh2[ntl >> 1][(ntl & 1) * 2];
#pragma unroll
                    for (int mt = 0; mt < 2; mt++)
                        hmma(acc[mt][g * 4 + ntl], al[mt], bhp);
                }
            }
        }
        sc = (sc + 1 == MM_STAGES) ? 0 : sc + 1;
        sp = (sp + 1 == MM_STAGES) ? 0 : sp + 1;
    }

    // ---------------- epilogue ----------------
    int r = lane >> 2, cq = (lane & 3) * 2;
    if (EPI == 3 && n0 + warpN * 64 >= 192) return;   // kqv pad cols dropped
#pragma unroll
    for (int mt = 0; mt < 2; mt++) {
#pragma unroll
        for (int half = 0; half < 2; half++) {
            long row = m0 + warpM * 32 + mt * 16 + half * 8 + r;
            if (EPI == 3) {
                long bt = row >> 3; int hh = (int)(row & 7);
                int bb = (int)(bt >> 12), tt = (int)(bt & 4095);
                float* kqrow = outf + row * 128;
                float* vrow  = vout + (((long)(bb * 8 + hh) * TDIM + tt) << 6);
#pragma unroll
                for (int nt = 0; nt < 8; nt++) {
                    int col = n0 + warpN * 64 + nt * 8 + cq;
                    float v0 = acc[mt][nt][half * 2 + 0] + bias[col];
                    float v1 = acc[mt][nt][half * 2 + 1] + bias[col + 1];
                    if (col < 128) *(float2*)(kqrow + col) = make_float2(v0, v1);
                    else           *(float2*)(vrow + col - 128) = make_float2(v0, v1);
                }
            } else {
#pragma unroll
                for (int nt = 0; nt < 8; nt++) {
                    int col = n0 + warpN * 64 + nt * 8 + cq;
                    float v0 = acc[mt][nt][half * 2 + 0] + bias[col];
                    float v1 = acc[mt][nt][half * 2 + 1] + bias[col + 1];
                    if (EPI == 1) {
                        v0 = gelu_f(v0); v1 = gelu_f(v1);
                        __nv_bfloat16 h0, l0, h1, l1;
                        split_bf16(v0, h0, l0); split_bf16(v1, h1, l1);
                        *(__nv_bfloat162*)(o_hi + row * N + col) = __halves2bfloat162(h0, h1);
                        *(__nv_bfloat162*)(o_lo + row * N + col) = __halves2bfloat162(l0, l1);
                    } else {
                        float2 rv = *(const float2*)(resid + row * N + col);
                        *(float2*)(outf + row * N + col) = make_float2(v0 + rv.x, v1 + rv.y);
                    }
                }
            }
        }
    }
}

// ---------------- weight split: f32 -> bf16 hi/lo, x4 vectorized ----------------
__global__ void split_kernel(const float* __restrict__ w, __nv_bfloat16* __restrict__ hi,
                             __nv_bfloat16* __restrict__ lo, int nvalid, int ntotal) {
    int i4 = (blockIdx.x * 256 + threadIdx.x) * 4;
    if (i4 < ntotal) {
        float4 v;
        if (i4 + 3 < nvalid) {
            v = *(const float4*)(w + i4);
        } else {
            v.x = (i4 + 0 < nvalid) ? w[i4 + 0] : 0.f;
            v.y = (i4 + 1 < nvalid) ? w[i4 + 1] : 0.f;
            v.z = (i4 + 2 < nvalid) ? w[i4 + 2] : 0.f;
            v.w = (i4 + 3 < nvalid) ? w[i4 + 3] : 0.f;
        }
        __nv_bfloat16 h0,l0,h1,l1,h2,l2,h3,l3;
        split_bf16(v.x,h0,l0); split_bf16(v.y,h1,l1);
        split_bf16(v.z,h2,l2); split_bf16(v.w,h3,l3);
        *(__nv_bfloat162*)(hi + i4)     = __halves2bfloat162(h0, h1);
        *(__nv_bfloat162*)(hi + i4 + 2) = __halves2bfloat162(h2, h3);
        *(__nv_bfloat162*)(lo + i4)     = __halves2bfloat162(l0, l1);
        *(__nv_bfloat162*)(lo + i4 + 2) = __halves2bfloat162(l2, l3);
    }
}

// ---------------- LayerNorm (bf16 hi/lo out) ----------------
__global__ void ln_split_kernel(const float* __restrict__ x, const float* __restrict__ g,
                                const float* __restrict__ b,
                                __nv_bfloat16* __restrict__ ohi, __nv_bfloat16* __restrict__ olo) {
    int wid = threadIdx.x >> 5, lane = threadIdx.x & 31;
    long row = (long)blockIdx.x * 8 + wid;
    const float4* xr = (const float4*)(x + row * EMBN);
    float4 v[4];
    float s = 0.f, sq = 0.f;
#pragma unroll
    for (int j = 0; j < 4; j++) {
        v[j] = xr[lane + 32 * j];
        s  += v[j].x + v[j].y + v[j].z + v[j].w;
        sq += v[j].x*v[j].x + v[j].y*v[j].y + v[j].z*v[j].z + v[j].w*v[j].w;
    }
#pragma unroll
    for (int o = 16; o; o >>= 1) {
        s  += __shfl_xor_sync(0xffffffffu, s,  o);
        sq += __shfl_xor_sync(0xffffffffu, sq, o);
    }
    float mu = s * (1.0f / EMBN);
    float var = sq * (1.0f / EMBN) - mu * mu;
    float rsv = rsqrtf(var + 1e-5f);
#pragma unroll
    for (int j = 0; j < 4; j++) {
        int fi = lane + 32 * j;
        float4 g4 = ((const float4*)g)[fi];
        float4 b4 = ((const float4*)b)[fi];
        float o0 = (v[j].x - mu) * rsv * g4.x + b4.x;
        float o1 = (v[j].y - mu) * rsv * g4.y + b4.y;
        float o2 = (v[j].z - mu) * rsv * g4.z + b4.z;
        float o3 = (v[j].w - mu) * rsv * g4.w + b4.w;
        __nv_bfloat16 h0,l0,h1,l1,h2,l2,h3,l3;
        split_bf16(o0,h0,l0); split_bf16(o1,h1,l1); split_bf16(o2,h2,l2); split_bf16(o3,h3,l3);
        long base = row * EMBN + fi * 4;
        *(__nv_bfloat162*)(ohi + base)     = __halves2bfloat162(h0, h1);
        *(__nv_bfloat162*)(ohi + base + 2) = __halves2bfloat162(h2, h3);
        *(__nv_bfloat162*)(olo + base)     = __halves2bfloat162(l0, l1);
        *(__nv_bfloat162*)(olo + base + 2) = __halves2bfloat162(l2, l3);
    }
}

// ---------------- prm_exp (k,q only; stride-128 input) ----------------
__global__ void prm_kernel(const float* __restrict__ kq, const float* __restrict__ w,
                           float* __restrict__ kp, float* __restrict__ qp) {
    __shared__ float w_s[32 * 65];
    __shared__ float z_s[8][128];
    int tid = threadIdx.x;
    for (int i = tid; i < MF * ES; i += 256)
        w_s[(i >> 6) * 65 + (i & 63)] = w[i];
    int wid = tid >> 5, lane = tid & 31;
    long row = (long)blockIdx.x * 8 + wid;
    const float* r = kq + row * 128;
    float k0 = r[lane],       k1 = r[lane + 32];
    float q0 = r[lane + 64],  q1 = r[lane + 96];
    int  h  = (int)(row & 7);
    long bt = row >> 3;
    int  b  = (int)(bt >> 12);
    int  t  = (int)(bt & 4095);
    z_s[wid][lane]      = k0;  z_s[wid][lane + 32] = k1;
    z_s[wid][64 + lane] = q0;  z_s[wid][96 + lane] = q1;
    float sk = k0 * k0 + k1 * k1;
    float sq = q0 * q0 + q1 * q1;
#pragma unroll
    for (int o = 16; o; o >>= 1) {
        sk += __shfl_xor_sync(0xffffffffu, sk, o);
        sq += __shfl_xor_sync(0xffffffffu, sq, o);
    }
    float xdk = 0.5f * sk, xdq = 0.5f * sq;
    __syncthreads();
    const float* wm = &w_s[lane * 65];
    float wk = 0.f, wq = 0.f;
#pragma unroll 8
    for (int e = 0; e < 64; e++) {
        float we = wm[e];
        wk += we * z_s[wid][e];
        wq += we * z_s[wid][64 + e];
    }
    const float rsM = 0.17677669529663687f;
    kp[((long)(b * 8 + h) * TDIM + t) * MF + lane] = expf(wk - xdk) * rsM;
    qp[row * MF + lane] = expf(wq - xdq) * rsM;
}

// ---------------- kptv[bh][e][m] = sum_t v[bh][t][e]*kp[bh][t][m]; ks = sum_t kp ----------------
// 16 segments of 256 tokens per bh
__global__ void kptv_kernel(const float* __restrict__ kp, const float* __restrict__ v,
                            float* __restrict__ kptv, float* __restrict__ ks) {
    int bh = blockIdx.x, seg = blockIdx.y;
    const float* kpb = kp + ((long)bh * TDIM + seg * 256) * MF;
    const float* vb  = v  + ((long)bh * TDIM + seg * 256) * ES;
    __shared__ float kc[16][32];
    __shared__ float vc[16][64];
    int tid = threadIdx.x;
    int m = tid & 31, eg = tid >> 5;
    unsigned long long acc2[4] = {0ull, 0ull, 0ull, 0ull};
    float ksa = 0.f;
    for (int c = 0; c < 16; c++) {
        __syncthreads();
#pragma unroll
        for (int i = 0; i < 2; i++) {
            int idx = tid + i * 256;
            kc[idx >> 5][idx & 31] = kpb[c * 512 + idx];
        }
#pragma unroll
        for (int i = 0; i < 4; i++) {
            int idx = tid + i * 256;
            vc[idx >> 6][idx & 63] = vb[c * 1024 + idx];
        }
        __syncthreads();
#pragma unroll
        for (int tt = 0; tt < 16; tt++) {
            float kv = kc[tt][m];
            if (eg == 0) ksa += kv;
            unsigned long long kv2 = pk2(kv);
#pragma unroll
            for (int j = 0; j < 4; j++)
                fma2(acc2[j], kv2, *(const unsigned long long*)&vc[tt][eg * 8 + j * 2]);
        }
    }
#pragma unroll
    for (int j = 0; j < 4; j++) {
        float a0, a1;
        upk2(acc2[j], a0, a1);
        atomicAdd(&kptv[(long)bh * (ES * MF) + (eg * 8 + j * 2) * MF + m], a0);
        atomicAdd(&kptv[(long)bh * (ES * MF) + (eg * 8 + j * 2 + 1) * MF + m], a1);
    }
    if (eg == 0) atomicAdd(&ks[bh * MF + m], ksa);
}

// ---------------- y = (qp @ kptv^T)/D -> bf16 hi/lo ----------------
__global__ void y_kernel(const float* __restrict__ qp, const float* __restrict__ kptv,
                         const float* __restrict__ ks,
                         __nv_bfloat16* __restrict__ yhi, __nv_bfloat16* __restrict__ ylo) {
    int tset = blockIdx.x, b = blockIdx.y, hh = blockIdx.z;
    __shared__ float kv_s[4 * 64 * 33];
    __shared__ float ks_s[4 * 32];
    int tid = threadIdx.x;
    for (int i = tid; i < 4 * 64 * 32; i += 256) {
        int h = i >> 11, e = (i >> 5) & 63, m = i & 31;
        kv_s[(h * 64 + e) * 33 + m] = kptv[((long)(b * 8 + hh * 4 + h) * 64 + e) * 32 + m];
    }
    if (tid < 128) ks_s[tid] = ks[(b * 8 + hh * 4) * 32 + tid];
    __syncthreads();
    int wid = tid >> 5, lane = tid & 31;
    int t = tset * 8 + wid;
    long row = (long)b * TDIM + t;
    const float* qpp = qp + row * (HEADSN * MF) + hh * 128;
    float qpr[4];
#pragma unroll
    for (int j = 0; j < 4; j++) qpr[j] = qpp[j * 32 + lane];
    long ybase = row * EMBN + hh * 256;
#pragma unroll
    for (int h = 0; h < 4; h++) {
        float d = qpr[h] * ks_s[h * 32 + lane];
#pragma unroll
        for (int o = 16; o; o >>= 1) d += __shfl_xor_sync(0xffffffffu, d, o);
        float invd = 1.0f / d;
        const float* kvh = &kv_s[h * 64 * 33];
        float a0 = 0.f, a1 = 0.f;
#pragma unroll 8
        for (int m = 0; m < 32; m++) {
            float qm = __shfl_sync(0xffffffffu, qpr[h], m);
            a0 += kvh[lane * 33 + m] * qm;
            a1 += kvh[(lane + 32) * 33 + m] * qm;
        }
        float o0 = a0 * invd, o1 = a1 * invd;
        __nv_bfloat16 h0, l0, h1, l1;
        split_bf16(o0, h0, l0); split_bf16(o1, h1, l1);
        yhi[ybase + h * 64 + lane]      = h0;
        ylo[ybase + h * 64 + lane]      = l0;
        yhi[ybase + h * 64 + 32 + lane] = h1;
        ylo[ybase + h * 64 + 32 + lane] = l1;
    }
}

// ---------------- launcher ----------------
extern "C" void kernel_launch(void* const* d_in, const int* in_sizes, int n_in,
                              void* d_out, int out_size) {
    const float* x      = (const float*)d_in[0];
    const float* w      = (const float*)d_in[1];
    const float* kqv_w  = (const float*)d_in[2];
    const float* kqv_b  = (const float*)d_in[3];
    const float* proj_w = (const float*)d_in[4];
    const float* proj_b = (const float*)d_in[5];
    const float* ln1_g  = (const float*)d_in[6];
    const float* ln1_b  = (const float*)d_in[7];
    const float* ln2_g  = (const float*)d_in[8];
    const float* ln2_b  = (const float*)d_in[9];
    const float* mlp_w1 = (const float*)d_in[10];
    const float* mlp_b1 = (const float*)d_in[11];
    const float* mlp_w2 = (const float*)d_in[12];
    const float* mlp_b2 = (const float*)d_in[13];
    float* out = (float*)d_out;

    float *pkq, *pkp, *pqp, *pv, *pks, *pkptv, *px1;
    __nv_bfloat16 *pyh, *pyl, *ph2h, *ph2l, *phdh, *phdl;
    __nv_bfloat16 *ppwh, *ppwl, *pw1h, *pw1l, *pw2h, *pw2l, *pkwh, *pkwl;
    cudaGetSymbolAddress((void**)&pkq,   g_kq);
    cudaGetSymbolAddress((void**)&pkp,   g_kp);
    cudaGetSymbolAddress((void**)&pqp,   g_qp);
    cudaGetSymbolAddress((void**)&pv,    g_v);
    cudaGetSymbolAddress((void**)&pks,   g_ks);
    cudaGetSymbolAddress((void**)&pkptv, g_kptv);
    cudaGetSymbolAddress((void**)&px1,   g_x1);
    cudaGetSymbolAddress((void**)&pyh,   g_y_hi);
    cudaGetSymbolAddress((void**)&pyl,   g_y_lo);
    cudaGetSymbolAddress((void**)&ph2h,  g_h2_hi);
    cudaGetSymbolAddress((void**)&ph2l,  g_h2_lo);
    cudaGetSymbolAddress((void**)&phdh,  g_hd_hi);
    cudaGetSymbolAddress((void**)&phdl,  g_hd_lo);
    cudaGetSymbolAddress((void**)&ppwh,  g_pw_hi);
    cudaGetSymbolAddress((void**)&ppwl,  g_pw_lo);
    cudaGetSymbolAddress((void**)&pw1h,  g_w1_hi);
    cudaGetSymbolAddress((void**)&pw1l,  g_w1_lo);
    cudaGetSymbolAddress((void**)&pw2h,  g_w2_hi);
    cudaGetSymbolAddress((void**)&pw2l,  g_w2_lo);
    cudaGetSymbolAddress((void**)&pkwh,  g_kw_hi);
    cudaGetSymbolAddress((void**)&pkwl,  g_kw_lo);

    cudaFuncSetAttribute(mm_gemm<1>, cudaFuncAttributeMaxDynamicSharedMemorySize, MM_SMEM);
    cudaFuncSetAttribute(mm_gemm<2>, cudaFuncAttributeMaxDynamicSharedMemorySize, MM_SMEM);
    cudaFuncSetAttribute(mm_gemm<3>, cudaFuncAttributeMaxDynamicSharedMemorySize, MM_SMEM);

    // zero reduction scratch (async memset is graph-capturable)
    cudaMemsetAsync(pkptv, 0, 64 * ES * MF * sizeof(float));
    cudaMemsetAsync(pks,   0, 64 * MF * sizeof(float));

    // weight splits (kqv_w padded 192 -> 256 rows), x4 vectorized
    split_kernel<<<(256*64/4 + 255)/256, 256>>>(kqv_w, pkwh, pkwl, 192*64, 256*64);
    split_kernel<<<(EMBN*EMBN/4 + 255)/256, 256>>>(proj_w, ppwh, ppwl, EMBN*EMBN, EMBN*EMBN);
    split_kernel<<<(HIDN*EMBN/4 + 255)/256, 256>>>(mlp_w1, pw1h, pw1l, HIDN*EMBN, HIDN*EMBN);
    split_kernel<<<(EMBN*HIDN/4 + 255)/256, 256>>>(mlp_w2, pw2h, pw2l, EMBN*HIDN, EMBN*HIDN);

    // 1) LN1 -> bf16 hi/lo
    ln_split_kernel<<<NTOK / 8, 256>>>(x, ln1_g, ln1_b, ph2h, ph2l);
    // 2) kqv GEMM (HMMA, EPI3): k|q -> g_kq, v -> g_v scatter (N padded to 256)
    mm_gemm<3><<<(NROWH/128) * 2, 256, MM_SMEM>>>(
        ph2h, ph2l, pkwh, pkwl, kqv_b, nullptr, pkq, nullptr, nullptr, pv, 256, 64);
    // 3) random features
    prm_kernel<<<NROWH / 8, 256>>>(pkq, w, pkp, pqp);
    // 4) kptv + ks (16 segments of 256 tokens)
    kptv_kernel<<<dim3(64, 16), 256>>>(pkp, pv, pkptv, pks);
    // 5) y -> bf16 hi/lo
    y_kernel<<<dim3(TDIM / 8, BDIM, 2), 256>>>(pqp, pkptv, pks, pyh, pyl);
    // 6) proj (HMMA) + bias + resid(x) -> x1
    mm_gemm<2><<<(NTOK/128) * (EMBN/128), 256, MM_SMEM>>>(
        pyh, pyl, ppwh, ppwl, proj_b, x, px1, nullptr, nullptr, nullptr, EMBN, EMBN);
    // 7) LN2 -> bf16 hi/lo
    ln_split_kernel<<<NTOK / 8, 256>>>(px1, ln2_g, ln2_b, ph2h, ph2l);
    // 8) MLP1 (HMMA) + bias + gelu -> hid bf16 hi/lo
    mm_gemm<1><<<(NTOK/128) * (HIDN/128), 256, MM_SMEM>>>(
        ph2h, ph2l, pw1h, pw1l, mlp_b1, nullptr, nullptr, phdh, phdl, nullptr, HIDN, EMBN);
    // 9) MLP2 (HMMA) + bias + resid(x1) -> out
    mm_gemm<2><<<(NTOK/128) * (EMBN/128), 256, MM_SMEM>>>(
        phdh, phdl, pw2h, pw2l, mlp_b2, px1, out, nullptr, nullptr, nullptr, EMBN, HIDN);
}

// round 17
// speedup vs baseline: 1.0948x; 1.0708x over previous
#include <cuda_runtime.h>
#include <cuda_bf16.h>
#include <math.h>
#include <stdint.h>

// ---------------- problem dims (fixed) ----------------
#define BDIM   8
#define TDIM   4096
#define HEADSN 8
#define ES     64
#define EMBN   512
#define MF     32
#define HIDN   2048
#define NTOK   (BDIM*TDIM)        // 32768
#define NROWH  (NTOK*HEADSN)      // 262144

// ---------------- scratch (device globals) ----------------
__device__ float g_kq  [NROWH*128];    // k|q per (token,head), stride 128
__device__ float g_kp  [NROWH*MF];
__device__ float g_qp  [NROWH*MF];
__device__ float g_v   [NROWH*ES];     // [b*8+h][t][e]
__device__ float g_ks  [64*MF];
__device__ float g_kptv[64*ES*MF];
__device__ float g_x1  [NTOK*EMBN];

__device__ __nv_bfloat16 g_y_hi [NTOK*EMBN];
__device__ __nv_bfloat16 g_y_lo [NTOK*EMBN];
__device__ __nv_bfloat16 g_h2_hi[NTOK*EMBN];   // LN1 out, then LN2 out (sequential reuse)
__device__ __nv_bfloat16 g_h2_lo[NTOK*EMBN];
__device__ __nv_bfloat16 g_hd_hi[NTOK*HIDN];
__device__ __nv_bfloat16 g_hd_lo[NTOK*HIDN];

__device__ __nv_bfloat16 g_pw_hi[EMBN*EMBN];
__device__ __nv_bfloat16 g_pw_lo[EMBN*EMBN];
__device__ __nv_bfloat16 g_w1_hi[HIDN*EMBN];
__device__ __nv_bfloat16 g_w1_lo[HIDN*EMBN];
__device__ __nv_bfloat16 g_w2_hi[EMBN*HIDN];
__device__ __nv_bfloat16 g_w2_lo[EMBN*HIDN];
__device__ __nv_bfloat16 g_kw_hi[256*64];      // kqv_w padded 192->256 rows
__device__ __nv_bfloat16 g_kw_lo[256*64];

// ---------------- helpers ----------------
__device__ __forceinline__ uint32_t smem_u32(const void* p) {
    uint32_t a;
    asm("{ .reg .u64 t; cvta.to.shared.u64 t, %1; cvt.u32.u64 %0, t; }" : "=r"(a) : "l"(p));
    return a;
}
__device__ __forceinline__ void cp16(uint32_t saddr, const void* g) {
    asm volatile("cp.async.cg.shared.global [%0], [%1], 16;" :: "r"(saddr), "l"(g) : "memory");
}
__device__ __forceinline__ void ldsm4(uint32_t* r, uint32_t addr) {
    asm volatile("ldmatrix.sync.aligned.m8n8.x4.shared.b16 {%0,%1,%2,%3}, [%4];"
        : "=r"(r[0]), "=r"(r[1]), "=r"(r[2]), "=r"(r[3]) : "r"(addr));
}
__device__ __forceinline__ void hmma(float* d, const uint32_t* a, const uint32_t* b) {
    asm volatile("mma.sync.aligned.m16n8k16.row.col.f32.bf16.bf16.f32 "
        "{%0,%1,%2,%3}, {%4,%5,%6,%7}, {%8,%9}, {%0,%1,%2,%3};"
        : "+f"(d[0]), "+f"(d[1]), "+f"(d[2]), "+f"(d[3])
        : "r"(a[0]), "r"(a[1]), "r"(a[2]), "r"(a[3]), "r"(b[0]), "r"(b[1]));
}
__device__ __forceinline__ float gelu_f(float v) {
    return 0.5f * v * (1.0f + erff(v * 0.7071067811865476f));
}
__device__ __forceinline__ void split_bf16(float v, __nv_bfloat16& hi, __nv_bfloat16& lo) {
    hi = __float2bfloat16(v);
    lo = __float2bfloat16(v - __bfloat162float(hi));
}
// f32x2 packed FMA
__device__ __forceinline__ unsigned long long pk2(float a) {
    unsigned long long r; unsigned int u = __float_as_uint(a);
    asm("mov.b64 %0, {%1, %1};" : "=l"(r) : "r"(u));
    return r;
}
__device__ __forceinline__ void fma2(unsigned long long& d, unsigned long long a, unsigned long long b) {
    asm("fma.rn.f32x2 %0, %1, %2, %0;" : "+l"(d) : "l"(a), "l"(b));
}
__device__ __forceinline__ void upk2(unsigned long long v, float& lo, float& hi) {
    unsigned int a, b;
    asm("mov.b64 {%0, %1}, %2;" : "=r"(a), "=r"(b) : "l"(v));
    lo = __uint_as_float(a); hi = __uint_as_float(b);
}

// ================= HMMA split-bf16 GEMM (128x128 CTA, 3 stages, occ 2, half-B regs) =================
// NPROD=3: hi*hi + hi*lo + lo*hi (full correction); NPROD=2: hi*hi + hi*lo (A-lo term dropped).
// EPI 1: o_hi/o_lo = bf16split(gelu(acc+bias))
// EPI 2: outf = acc+bias+resid (f32)
// EPI 3: kqv: cols<128 -> outf (k|q, stride 128); 128..191 -> vout scatter; >=192 dropped
#define MM_STAGES 3
#define MM_STAGE_BYTES 32768     // A hi/lo 8KB+8KB, B hi/lo 8KB+8KB
#define MM_SMEM (MM_STAGES * MM_STAGE_BYTES)

__device__ __forceinline__ uint32_t swz(int row, int chunk) {
    return (uint32_t)(row * 64 + ((chunk ^ ((row >> 1) & 3)) << 4));
}
__device__ __forceinline__ uint32_t addrA(uint32_t base, int lane, int ks) {
    int grp = lane >> 3;
    int row = (lane & 7) + ((grp & 1) << 3);
    int chunk = (ks << 1) + (grp >> 1);
    return base + swz(row, chunk);
}
__device__ __forceinline__ uint32_t addrB(uint32_t base, int lane, int ks) {
    int grp = lane >> 3;
    int row = (lane & 7) + ((grp >> 1) << 3);
    int chunk = (ks << 1) + (grp & 1);
    return base + swz(row, chunk);
}

__device__ __forceinline__ void mm_load_stage(
    uint32_t st, const char* Ah, const char* Al, const char* Bh, const char* Bl,
    long rsb, long kb2, int tid) {
    int lr = tid >> 1, lc0 = (tid & 1) * 2;
    long go = (long)lr * rsb + kb2;
#pragma unroll
    for (int j = 0; j < 2; j++) {
        int c = lc0 + j;
        uint32_t sw = swz(lr, c);
        cp16(st + sw,         Ah + go + c * 16);
        cp16(st + 8192 + sw,  Al + go + c * 16);
        cp16(st + 16384 + sw, Bh + go + c * 16);
        cp16(st + 24576 + sw, Bl + go + c * 16);
    }
}

template<int EPI, int NPROD>
__global__ void __launch_bounds__(256, 2)
mm_gemm(const __nv_bfloat16* __restrict__ a_hi, const __nv_bfloat16* __restrict__ a_lo,
        const __nv_bfloat16* __restrict__ w_hi, const __nv_bfloat16* __restrict__ w_lo,
        const float* __restrict__ bias, const float* __restrict__ resid,
        float* __restrict__ outf, __nv_bfloat16* __restrict__ o_hi, __nv_bfloat16* __restrict__ o_lo,
        float* __restrict__ vout, int N, int K) {
    extern __shared__ char smem[];
    uint32_t sb = smem_u32(smem);
    int tid = threadIdx.x, wid = tid >> 5, lane = tid & 31;

    // supertile swizzle: 16 M-tiles per group
    int gn = N >> 7;
    int per = 16 * gn;
    int grp_ = blockIdx.x / per, rem = blockIdx.x - grp_ * per;
    int m0 = (grp_ * 16 + (rem & 15)) * 128;
    int n0 = (rem >> 4) * 128;

    const long rsb = (long)K * 2;
    const char* Ah = (const char*)a_hi + (long)m0 * rsb;
    const char* Al = (const char*)a_lo + (long)m0 * rsb;
    const char* Bh = (const char*)w_hi + (long)n0 * rsb;
    const char* Bl = (const char*)w_lo + (long)n0 * rsb;
    int KT = K >> 5;

    // prologue: fill STAGES-1 stages
#pragma unroll
    for (int s = 0; s < MM_STAGES - 1; s++) {
        if (s < KT) mm_load_stage(sb + s * MM_STAGE_BYTES, Ah, Al, Bh, Bl, rsb, (long)s * 64, tid);
        asm volatile("cp.async.commit_group;" ::: "memory");
    }

    int warpM = wid & 3, warpN = wid >> 2;
    float acc[2][8][4];
#pragma unroll
    for (int mt = 0; mt < 2; mt++)
#pragma unroll
        for (int nt = 0; nt < 8; nt++)
#pragma unroll
            for (int q = 0; q < 4; q++) acc[mt][nt][q] = 0.f;

    int sc = 0, sp = MM_STAGES - 1;
    for (int kt = 0; kt < KT; kt++) {
        asm volatile("cp.async.wait_group %0;" :: "n"(MM_STAGES - 2) : "memory");
        __syncthreads();
        int pf = kt + MM_STAGES - 1;
        if (pf < KT)
            mm_load_stage(sb + sp * MM_STAGE_BYTES, Ah, Al, Bh, Bl, rsb, (long)pf * 64, tid);
        asm volatile("cp.async.commit_group;" ::: "memory");

        uint32_t st = sb + sc * MM_STAGE_BYTES;
        uint32_t aH = st + (warpM * 32) * 64;
        uint32_t aL = aH + 8192;
        uint32_t bH = st + 16384 + (warpN * 64) * 64;
        uint32_t bL = bH + 8192;

#pragma unroll
        for (int ks = 0; ks < 2; ks++) {
            uint32_t ah[2][4], al[2][4];
#pragma unroll
            for (int mt = 0; mt < 2; mt++) {
                ldsm4(ah[mt], addrA(aH + mt * 16 * 64, lane, ks));
                if (NPROD == 3) ldsm4(al[mt], addrA(aL + mt * 16 * 64, lane, ks));
            }
            // B in two halves (register cap for occ 2); product-major hmma order
#pragma unroll
            for (int g = 0; g < 2; g++) {
                uint32_t bh2[2][4], bl2[2][4];
#pragma unroll
                for (int j = 0; j < 2; j++) {
                    ldsm4(bh2[j], addrB(bH + (g * 2 + j) * 1024, lane, ks));
                    ldsm4(bl2[j], addrB(bL + (g * 2 + j) * 1024, lane, ks));
                }
                // group 1: a_hi * b_hi  (independent accumulators)
#pragma unroll
                for (int ntl = 0; ntl < 4; ntl++) {
                    const uint32_t* bhp = &bh2[ntl >> 1][(ntl & 1) * 2];
#pragma unroll
                    for (int mt = 0; mt < 2; mt++)
                        hmma(acc[mt][g * 4 + ntl], ah[mt], bhp);
                }
                // group 2: a_hi * b_lo
#pragma unroll
                for (int ntl = 0; ntl < 4; ntl++) {
                    const uint32_t* blp = &bl2[ntl >> 1][(ntl & 1) * 2];
#pragma unroll
                    for (int mt = 0; mt < 2; mt++)
                        hmma(acc[mt][g * 4 + ntl], ah[mt], blp);
                }
                // group 3: a_lo * b_hi (full-correction variants only)
                if (NPROD == 3) {
#pragma unroll
                    for (int ntl = 0; ntl < 4; ntl++) {
                        const uint32_t* bhp = &bh2[ntl >> 1][(ntl & 1) * 2];
#pragma unroll
                        for (int mt = 0; mt < 2; mt++)
                            hmma(acc[mt][g * 4 + ntl], al[mt], bhp);
                    }
                }
            }
        }
        sc = (sc + 1 == MM_STAGES) ? 0 : sc + 1;
        sp = (sp + 1 == MM_STAGES) ? 0 : sp + 1;
    }

    // ---------------- epilogue ----------------
    int r = lane >> 2, cq = (lane & 3) * 2;
    if (EPI == 3 && n0 + warpN * 64 >= 192) return;   // kqv pad cols dropped
#pragma unroll
    for (int mt = 0; mt < 2; mt++) {
#pragma unroll
        for (int half = 0; half < 2; half++) {
            long row = m0 + warpM * 32 + mt * 16 + half * 8 + r;
            if (EPI == 3) {
                long bt = row >> 3; int hh = (int)(row & 7);
                int bb = (int)(bt >> 12), tt = (int)(bt & 4095);
                float* kqrow = outf + row * 128;
                float* vrow  = vout + (((long)(bb * 8 + hh) * TDIM + tt) << 6);
#pragma unroll
                for (int nt = 0; nt < 8; nt++) {
                    int col = n0 + warpN * 64 + nt * 8 + cq;
                    float v0 = acc[mt][nt][half * 2 + 0] + bias[col];
                    float v1 = acc[mt][nt][half * 2 + 1] + bias[col + 1];
                    if (col < 128) *(float2*)(kqrow + col) = make_float2(v0, v1);
                    else           *(float2*)(vrow + col - 128) = make_float2(v0, v1);
                }
            } else {
#pragma unroll
                for (int nt = 0; nt < 8; nt++) {
                    int col = n0 + warpN * 64 + nt * 8 + cq;
                    float v0 = acc[mt][nt][half * 2 + 0] + bias[col];
                    float v1 = acc[mt][nt][half * 2 + 1] + bias[col + 1];
                    if (EPI == 1) {
                        v0 = gelu_f(v0); v1 = gelu_f(v1);
                        __nv_bfloat16 h0, l0, h1, l1;
                        split_bf16(v0, h0, l0); split_bf16(v1, h1, l1);
                        *(__nv_bfloat162*)(o_hi + row * N + col) = __halves2bfloat162(h0, h1);
                        *(__nv_bfloat162*)(o_lo + row * N + col) = __halves2bfloat162(l0, l1);
                    } else {
                        float2 rv = *(const float2*)(resid + row * N + col);
                        *(float2*)(outf + row * N + col) = make_float2(v0 + rv.x, v1 + rv.y);
                    }
                }
            }
        }
    }
}

// ---------------- weight split: f32 -> bf16 hi/lo, x4 vectorized ----------------
__global__ void split_kernel(const float* __restrict__ w, __nv_bfloat16* __restrict__ hi,
                             __nv_bfloat16* __restrict__ lo, int nvalid, int ntotal) {
    int i4 = (blockIdx.x * 256 + threadIdx.x) * 4;
    if (i4 < ntotal) {
        float4 v;
        if (i4 + 3 < nvalid) {
            v = *(const float4*)(w + i4);
        } else {
            v.x = (i4 + 0 < nvalid) ? w[i4 + 0] : 0.f;
            v.y = (i4 + 1 < nvalid) ? w[i4 + 1] : 0.f;
            v.z = (i4 + 2 < nvalid) ? w[i4 + 2] : 0.f;
            v.w = (i4 + 3 < nvalid) ? w[i4 + 3] : 0.f;
        }
        __nv_bfloat16 h0,l0,h1,l1,h2,l2,h3,l3;
        split_bf16(v.x,h0,l0); split_bf16(v.y,h1,l1);
        split_bf16(v.z,h2,l2); split_bf16(v.w,h3,l3);
        *(__nv_bfloat162*)(hi + i4)     = __halves2bfloat162(h0, h1);
        *(__nv_bfloat162*)(hi + i4 + 2) = __halves2bfloat162(h2, h3);
        *(__nv_bfloat162*)(lo + i4)     = __halves2bfloat162(l0, l1);
        *(__nv_bfloat162*)(lo + i4 + 2) = __halves2bfloat162(l2, l3);
    }
}

// ---------------- LayerNorm (bf16 hi/lo out) ----------------
__global__ void ln_split_kernel(const float* __restrict__ x, const float* __restrict__ g,
                                const float* __restrict__ b,
                                __nv_bfloat16* __restrict__ ohi, __nv_bfloat16* __restrict__ olo) {
    int wid = threadIdx.x >> 5, lane = threadIdx.x & 31;
    long row = (long)blockIdx.x * 8 + wid;
    const float4* xr = (const float4*)(x + row * EMBN);
    float4 v[4];
    float s = 0.f, sq = 0.f;
#pragma unroll
    for (int j = 0; j < 4; j++) {
        v[j] = xr[lane + 32 * j];
        s  += v[j].x + v[j].y + v[j].z + v[j].w;
        sq += v[j].x*v[j].x + v[j].y*v[j].y + v[j].z*v[j].z + v[j].w*v[j].w;
    }
#pragma unroll
    for (int o = 16; o; o >>= 1) {
        s  += __shfl_xor_sync(0xffffffffu, s,  o);
        sq += __shfl_xor_sync(0xffffffffu, sq, o);
    }
    float mu = s * (1.0f / EMBN);
    float var = sq * (1.0f / EMBN) - mu * mu;
    float rsv = rsqrtf(var + 1e-5f);
#pragma unroll
    for (int j = 0; j < 4; j++) {
        int fi = lane + 32 * j;
        float4 g4 = ((const float4*)g)[fi];
        float4 b4 = ((const float4*)b)[fi];
        float o0 = (v[j].x - mu) * rsv * g4.x + b4.x;
        float o1 = (v[j].y - mu) * rsv * g4.y + b4.y;
        float o2 = (v[j].z - mu) * rsv * g4.z + b4.z;
        float o3 = (v[j].w - mu) * rsv * g4.w + b4.w;
        __nv_bfloat16 h0,l0,h1,l1,h2,l2,h3,l3;
        split_bf16(o0,h0,l0); split_bf16(o1,h1,l1); split_bf16(o2,h2,l2); split_bf16(o3,h3,l3);
        long base = row * EMBN + fi * 4;
        *(__nv_bfloat162*)(ohi + base)     = __halves2bfloat162(h0, h1);
        *(__nv_bfloat162*)(ohi + base + 2) = __halves2bfloat162(h2, h3);
        *(__nv_bfloat162*)(olo + base)     = __halves2bfloat162(l0, l1);
        *(__nv_bfloat162*)(olo + base + 2) = __halves2bfloat162(l2, l3);
    }
}

// ---------------- prm_exp (k,q only; stride-128 input) ----------------
__global__ void prm_kernel(const float* __restrict__ kq, const float* __restrict__ w,
                           float* __restrict__ kp, float* __restrict__ qp) {
    __shared__ float w_s[32 * 65];
    __shared__ float z_s[8][128];
    int tid = threadIdx.x;
    for (int i = tid; i < MF * ES; i += 256)
        w_s[(i >> 6) * 65 + (i & 63)] = w[i];
    int wid = tid >> 5, lane = tid & 31;
    long row = (long)blockIdx.x * 8 + wid;
    const float* r = kq + row * 128;
    float k0 = r[lane],       k1 = r[lane + 32];
    float q0 = r[lane + 64],  q1 = r[lane + 96];
    int  h  = (int)(row & 7);
    long bt = row >> 3;
    int  b  = (int)(bt >> 12);
    int  t  = (int)(bt & 4095);
    z_s[wid][lane]      = k0;  z_s[wid][lane + 32] = k1;
    z_s[wid][64 + lane] = q0;  z_s[wid][96 + lane] = q1;
    float sk = k0 * k0 + k1 * k1;
    float sq = q0 * q0 + q1 * q1;
#pragma unroll
    for (int o = 16; o; o >>= 1) {
        sk += __shfl_xor_sync(0xffffffffu, sk, o);
        sq += __shfl_xor_sync(0xffffffffu, sq, o);
    }
    float xdk = 0.5f * sk, xdq = 0.5f * sq;
    __syncthreads();
    const float* wm = &w_s[lane * 65];
    float wk = 0.f, wq = 0.f;
#pragma unroll 8
    for (int e = 0; e < 64; e++) {
        float we = wm[e];
        wk += we * z_s[wid][e];
        wq += we * z_s[wid][64 + e];
    }
    const float rsM = 0.17677669529663687f;
    kp[((long)(b * 8 + h) * TDIM + t) * MF + lane] = expf(wk - xdk) * rsM;
    qp[row * MF + lane] = expf(wq - xdq) * rsM;
}

// ---------------- kptv[bh][e][m] = sum_t v[bh][t][e]*kp[bh][t][m]; ks = sum_t kp ----------------
// 16 segments of 256 tokens per bh
__global__ void kptv_kernel(const float* __restrict__ kp, const float* __restrict__ v,
                            float* __restrict__ kptv, float* __restrict__ ks) {
    int bh = blockIdx.x, seg = blockIdx.y;
    const float* kpb = kp + ((long)bh * TDIM + seg * 256) * MF;
    const float* vb  = v  + ((long)bh * TDIM + seg * 256) * ES;
    __shared__ float kc[16][32];
    __shared__ float vc[16][64];
    int tid = threadIdx.x;
    int m = tid & 31, eg = tid >> 5;
    unsigned long long acc2[4] = {0ull, 0ull, 0ull, 0ull};
    float ksa = 0.f;
    for (int c = 0; c < 16; c++) {
        __syncthreads();
#pragma unroll
        for (int i = 0; i < 2; i++) {
            int idx = tid + i * 256;
            kc[idx >> 5][idx & 31] = kpb[c * 512 + idx];
        }
#pragma unroll
        for (int i = 0; i < 4; i++) {
            int idx = tid + i * 256;
            vc[idx >> 6][idx & 63] = vb[c * 1024 + idx];
        }
        __syncthreads();
#pragma unroll
        for (int tt = 0; tt < 16; tt++) {
            float kv = kc[tt][m];
            if (eg == 0) ksa += kv;
            unsigned long long kv2 = pk2(kv);
#pragma unroll
            for (int j = 0; j < 4; j++)
                fma2(acc2[j], kv2, *(const unsigned long long*)&vc[tt][eg * 8 + j * 2]);
        }
    }
#pragma unroll
    for (int j = 0; j < 4; j++) {
        float a0, a1;
        upk2(acc2[j], a0, a1);
        atomicAdd(&kptv[(long)bh * (ES * MF) + (eg * 8 + j * 2) * MF + m], a0);
        atomicAdd(&kptv[(long)bh * (ES * MF) + (eg * 8 + j * 2 + 1) * MF + m], a1);
    }
    if (eg == 0) atomicAdd(&ks[bh * MF + m], ksa);
}

// ---------------- y = (qp @ kptv^T)/D -> bf16 hi/lo ----------------
__global__ void y_kernel(const float* __restrict__ qp, const float* __restrict__ kptv,
                         const float* __restrict__ ks,
                         __nv_bfloat16* __restrict__ yhi, __nv_bfloat16* __restrict__ ylo) {
    int tset = blockIdx.x, b = blockIdx.y, hh = blockIdx.z;
    __shared__ float kv_s[4 * 64 * 33];
    __shared__ float ks_s[4 * 32];
    int tid = threadIdx.x;
    for (int i = tid; i < 4 * 64 * 32; i += 256) {
        int h = i >> 11, e = (i >> 5) & 63, m = i & 31;
        kv_s[(h * 64 + e) * 33 + m] = kptv[((long)(b * 8 + hh * 4 + h) * 64 + e) * 32 + m];
    }
    if (tid < 128) ks_s[tid] = ks[(b * 8 + hh * 4) * 32 + tid];
    __syncthreads();
    int wid = tid >> 5, lane = tid & 31;
    int t = tset * 8 + wid;
    long row = (long)b * TDIM + t;
    const float* qpp = qp + row * (HEADSN * MF) + hh * 128;
    float qpr[4];
#pragma unroll
    for (int j = 0; j < 4; j++) qpr[j] = qpp[j * 32 + lane];
    long ybase = row * EMBN + hh * 256;
#pragma unroll
    for (int h = 0; h < 4; h++) {
        float d = qpr[h] * ks_s[h * 32 + lane];
#pragma unroll
        for (int o = 16; o; o >>= 1) d += __shfl_xor_sync(0xffffffffu, d, o);
        float invd = 1.0f / d;
        const float* kvh = &kv_s[h * 64 * 33];
        float a0 = 0.f, a1 = 0.f;
#pragma unroll 8
        for (int m = 0; m < 32; m++) {
            float qm = __shfl_sync(0xffffffffu, qpr[h], m);
            a0 += kvh[lane * 33 + m] * qm;
            a1 += kvh[(lane + 32) * 33 + m] * qm;
        }
        float o0 = a0 * invd, o1 = a1 * invd;
        __nv_bfloat16 h0, l0, h1, l1;
        split_bf16(o0, h0, l0); split_bf16(o1, h1, l1);
        yhi[ybase + h * 64 + lane]      = h0;
        ylo[ybase + h * 64 + lane]      = l0;
        yhi[ybase + h * 64 + 32 + lane] = h1;
        ylo[ybase + h * 64 + 32 + lane] = l1;
    }
}

// ---------------- launcher ----------------
extern "C" void kernel_launch(void* const* d_in, const int* in_sizes, int n_in,
                              void* d_out, int out_size) {
    const float* x      = (const float*)d_in[0];
    const float* w      = (const float*)d_in[1];
    const float* kqv_w  = (const float*)d_in[2];
    const float* kqv_b  = (const float*)d_in[3];
    const float* proj_w = (const float*)d_in[4];
    const float* proj_b = (const float*)d_in[5];
    const float* ln1_g  = (const float*)d_in[6];
    const float* ln1_b  = (const float*)d_in[7];
    const float* ln2_g  = (const float*)d_in[8];
    const float* ln2_b  = (const float*)d_in[9];
    const float* mlp_w1 = (const float*)d_in[10];
    const float* mlp_b1 = (const float*)d_in[11];
    const float* mlp_w2 = (const float*)d_in[12];
    const float* mlp_b2 = (const float*)d_in[13];
    float* out = (float*)d_out;

    float *pkq, *pkp, *pqp, *pv, *pks, *pkptv, *px1;
    __nv_bfloat16 *pyh, *pyl, *ph2h, *ph2l, *phdh, *phdl;
    __nv_bfloat16 *ppwh, *ppwl, *pw1h, *pw1l, *pw2h, *pw2l, *pkwh, *pkwl;
    cudaGetSymbolAddress((void**)&pkq,   g_kq);
    cudaGetSymbolAddress((void**)&pkp,   g_kp);
    cudaGetSymbolAddress((void**)&pqp,   g_qp);
    cudaGetSymbolAddress((void**)&pv,    g_v);
    cudaGetSymbolAddress((void**)&pks,   g_ks);
    cudaGetSymbolAddress((void**)&pkptv, g_kptv);
    cudaGetSymbolAddress((void**)&px1,   g_x1);
    cudaGetSymbolAddress((void**)&pyh,   g_y_hi);
    cudaGetSymbolAddress((void**)&pyl,   g_y_lo);
    cudaGetSymbolAddress((void**)&ph2h,  g_h2_hi);
    cudaGetSymbolAddress((void**)&ph2l,  g_h2_lo);
    cudaGetSymbolAddress((void**)&phdh,  g_hd_hi);
    cudaGetSymbolAddress((void**)&phdl,  g_hd_lo);
    cudaGetSymbolAddress((void**)&ppwh,  g_pw_hi);
    cudaGetSymbolAddress((void**)&ppwl,  g_pw_lo);
    cudaGetSymbolAddress((void**)&pw1h,  g_w1_hi);
    cudaGetSymbolAddress((void**)&pw1l,  g_w1_lo);
    cudaGetSymbolAddress((void**)&pw2h,  g_w2_hi);
    cudaGetSymbolAddress((void**)&pw2l,  g_w2_lo);
    cudaGetSymbolAddress((void**)&pkwh,  g_kw_hi);
    cudaGetSymbolAddress((void**)&pkwl,  g_kw_lo);

    cudaFuncSetAttribute((const void*)mm_gemm<1,2>, cudaFuncAttributeMaxDynamicSharedMemorySize, MM_SMEM);
    cudaFuncSetAttribute((const void*)mm_gemm<2,3>, cudaFuncAttributeMaxDynamicSharedMemorySize, MM_SMEM);
    cudaFuncSetAttribute((const void*)mm_gemm<3,3>, cudaFuncAttributeMaxDynamicSharedMemorySize, MM_SMEM);

    // zero reduction scratch (async memset is graph-capturable)
    cudaMemsetAsync(pkptv, 0, 64 * ES * MF * sizeof(float));
    cudaMemsetAsync(pks,   0, 64 * MF * sizeof(float));

    // weight splits (kqv_w padded 192 -> 256 rows), x4 vectorized
    split_kernel<<<(256*64/4 + 255)/256, 256>>>(kqv_w, pkwh, pkwl, 192*64, 256*64);
    split_kernel<<<(EMBN*EMBN/4 + 255)/256, 256>>>(proj_w, ppwh, ppwl, EMBN*EMBN, EMBN*EMBN);
    split_kernel<<<(HIDN*EMBN/4 + 255)/256, 256>>>(mlp_w1, pw1h, pw1l, HIDN*EMBN, HIDN*EMBN);
    split_kernel<<<(EMBN*HIDN/4 + 255)/256, 256>>>(mlp_w2, pw2h, pw2l, EMBN*HIDN, EMBN*HIDN);

    // 1) LN1 -> bf16 hi/lo
    ln_split_kernel<<<NTOK / 8, 256>>>(x, ln1_g, ln1_b, ph2h, ph2l);
    // 2) kqv GEMM (HMMA, EPI3, 3-product): k|q -> g_kq, v -> g_v scatter (N padded to 256)
    mm_gemm<3,3><<<(NROWH/128) * 2, 256, MM_SMEM>>>(
        ph2h, ph2l, pkwh, pkwl, kqv_b, nullptr, pkq, nullptr, nullptr, pv, 256, 64);
    // 3) random features
    prm_kernel<<<NROWH / 8, 256>>>(pkq, w, pkp, pqp);
    // 4) kptv + ks (16 segments of 256 tokens)
    kptv_kernel<<<dim3(64, 16), 256>>>(pkp, pv, pkptv, pks);
    // 5) y -> bf16 hi/lo
    y_kernel<<<dim3(TDIM / 8, BDIM, 2), 256>>>(pqp, pkptv, pks, pyh, pyl);
    // 6) proj (HMMA, 3-product) + bias + resid(x) -> x1
    mm_gemm<2,3><<<(NTOK/128) * (EMBN/128), 256, MM_SMEM>>>(
        pyh, pyl, ppwh, ppwl, proj_b, x, px1, nullptr, nullptr, nullptr, EMBN, EMBN);
    // 7) LN2 -> bf16 hi/lo
    ln_split_kernel<<<NTOK / 8, 256>>>(px1, ln2_g, ln2_b, ph2h, ph2l);
    // 8) MLP1 (HMMA, 2-product) + bias + gelu -> hid bf16 hi/lo
    mm_gemm<1,2><<<(NTOK/128) * (HIDN/128), 256, MM_SMEM>>>(
        ph2h, ph2l, pw1h, pw1l, mlp_b1, nullptr, nullptr, phdh, phdl, nullptr, HIDN, EMBN);
    // 9) MLP2 (HMMA, 3-product) + bias + resid(x1) -> out
    mm_gemm<2,3><<<(NTOK/128) * (EMBN/128), 256, MM_SMEM>>>(
        phdh, phdl, pw2h, pw2l, mlp_b2, px1, out, nullptr, nullptr, nullptr, EMBN, HIDN);
}